// round 1
// baseline (speedup 1.0000x reference)
#include <cuda_runtime.h>
#include <math.h>

// Problem constants (fixed by the dataset):
//   B=128, L=8192, NF=16, D=256, NC=4
//   FFT bin indices for CYCLES [1/12,1/4,1/2,1] @ SR=1/30, L=8192:
//   k = {23, 68, 137, 273}
// Inputs (metadata order):
//   d_in[0] input_sequence (B,L,NF) f32   -- only channel 0 used
//   d_in[1] hidden_states  (B,L,D)  f32   -- UNUSED by reference; never read
//   d_in[2] cycle_weights  (NC,)    f32
//   d_in[3] proj_w         (D,2*NC) f32
//   d_in[4] proj_b         (D,)     f32
// Output: (B,D) f32

#define BB   128
#define LL   8192
#define NFF  16
#define DD   256
#define NCC  4
#define TPB  256

__global__ __launch_bounds__(TPB)
void cycle_detector_kernel(const float* __restrict__ seq,
                           const float* __restrict__ cw,
                           const float* __restrict__ pw,   // (D, 8) row-major
                           const float* __restrict__ pb,
                           float* __restrict__ out)
{
    const int b   = blockIdx.x;
    const int tid = threadIdx.x;

    const int KIDX[NCC] = {23, 68, 137, 273};
    const float TWO_PI = 6.28318530717958647692f;

    float re[NCC], im[NCC];
    float cr[NCC], ci[NCC];   // current twiddle e^{-2pi i k t / L}
    float dr[NCC], di[NCC];   // step twiddle e^{-2pi i k*TPB / L}

#pragma unroll
    for (int j = 0; j < NCC; j++) {
        re[j] = 0.0f; im[j] = 0.0f;
        int m0 = (KIDX[j] * tid) & (LL - 1);
        float th0 = -TWO_PI * (float)m0 * (1.0f / (float)LL);
        sincosf(th0, &ci[j], &cr[j]);
        int md = (KIDX[j] * TPB) & (LL - 1);
        float thd = -TWO_PI * (float)md * (1.0f / (float)LL);
        sincosf(thd, &di[j], &dr[j]);
    }

    // claims[b, t, 0], t = tid + TPB*i
    const float* base = seq + (size_t)b * (size_t)(LL * NFF) + (size_t)tid * NFF;

#pragma unroll 8
    for (int i = 0; i < LL / TPB; i++) {
        float x = __ldg(base + (size_t)i * (TPB * NFF));
#pragma unroll
        for (int j = 0; j < NCC; j++) {
            re[j] = fmaf(x, cr[j], re[j]);
            im[j] = fmaf(x, ci[j], im[j]);
            // rotate twiddle by step
            float cn = cr[j] * dr[j] - ci[j] * di[j];
            ci[j]    = fmaf(ci[j], dr[j], cr[j] * di[j]);
            cr[j]    = cn;
        }
    }

    // ---- block reduction of 8 partials (re[0..3], im[0..3]) ----
#pragma unroll
    for (int off = 16; off > 0; off >>= 1) {
#pragma unroll
        for (int j = 0; j < NCC; j++) {
            re[j] += __shfl_xor_sync(0xffffffffu, re[j], off);
            im[j] += __shfl_xor_sync(0xffffffffu, im[j], off);
        }
    }

    __shared__ float sred[8][8];    // [warp][val: re0..3, im0..3]
    __shared__ float sbin[8];       // re0..3, im0..3 (final)
    __shared__ float fwsh[8];       // weighted features (mag,phase interleaved)

    const int wid  = tid >> 5;
    const int lane = tid & 31;
    if (lane == 0) {
#pragma unroll
        for (int j = 0; j < NCC; j++) {
            sred[wid][j]       = re[j];
            sred[wid][4 + j]   = im[j];
        }
    }
    __syncthreads();

    if (tid < 8) {
        float v = 0.0f;
#pragma unroll
        for (int w = 0; w < 8; w++) v += sred[w][tid];
        sbin[tid] = v;
    }
    __syncthreads();

    if (tid < NCC) {
        float R = sbin[tid];
        float I = sbin[4 + tid];
        float mag = sqrtf(fmaf(R, R, I * I));
        float ph  = atan2f(I, R);
        float w   = cw[tid];
        fwsh[2 * tid]     = mag * w;
        fwsh[2 * tid + 1] = ph * w;
    }
    __syncthreads();

    // ---- projection: out[b,d] = pb[d] + sum_j fwsh[j] * pw[d*8 + j] ----
    float acc = pb[tid];
    const float* pwrow = pw + tid * (2 * NCC);
#pragma unroll
    for (int j = 0; j < 2 * NCC; j++)
        acc = fmaf(fwsh[j], pwrow[j], acc);

    out[b * DD + tid] = acc;
}

extern "C" void kernel_launch(void* const* d_in, const int* in_sizes, int n_in,
                              void* d_out, int out_size)
{
    const float* seq = (const float*)d_in[0];
    // d_in[1] = hidden_states: intentionally unused (reference never reads it)
    const float* cw  = (const float*)d_in[2];
    const float* pw  = (const float*)d_in[3];
    const float* pb  = (const float*)d_in[4];
    float* out       = (float*)d_out;

    cycle_detector_kernel<<<BB, TPB>>>(seq, cw, pw, pb, out);
}